// round 2
// baseline (speedup 1.0000x reference)
#include <cuda_runtime.h>

#define NTOK 65536
#define DDIM 512
#define KT 512
#define KE 256
#define KD 512
#define KTOT (KT + KE + KD + KD)

// ---------------- scratch (device globals; no runtime alloc) ----------------
__device__ float g_tfeat[(size_t)NTOK * DDIM];
__device__ float g_efeat[(size_t)NTOK * DDIM];
__device__ float g_dfeat[(size_t)NTOK * DDIM];
__device__ float g_resid[(size_t)NTOK * DDIM];
__device__ float g_rown[4 * NTOK];          // |f|^2 per token per stage (t,e,d,resid)
__device__ int   g_idx[4 * NTOK];           // argmin indices per stage
__device__ float g_E[(size_t)KTOT * DDIM];  // projected codebooks Et,Ee,E0,E1
__device__ float g_cn[KTOT];                // |c|^2 per code
__device__ float g_lacc[4];                 // loss sum accumulators

// ---------------- generic fp32 SGEMM:  C[m][n] = sum_k A[m*lda+k]*B[n*ldb+k] (+bias[n]) ----
#define BM 64
#define BN 64
#define BK 16

__global__ __launch_bounds__(256) void sgemm_bias(
    const float* __restrict__ A, int lda,
    const float* __restrict__ B, int ldb,
    const float* __restrict__ bias,
    float* __restrict__ C, int ldc, int Kd)
{
    __shared__ float As[BK][BM + 4];
    __shared__ float Bs[BK][BN + 4];
    int t = threadIdx.x;
    int tx = t & 15, ty = t >> 4;
    int row0 = blockIdx.y * BM;
    int col0 = blockIdx.x * BN;
    int lr = t >> 2;
    int lk = (t & 3) << 2;
    const float* Ap = A + (size_t)(row0 + lr) * lda + lk;
    const float* Bp = B + (size_t)(col0 + lr) * ldb + lk;
    float acc[4][4] = {};
    for (int k0 = 0; k0 < Kd; k0 += BK) {
        float4 av = *(const float4*)(Ap + k0);
        float4 bv = *(const float4*)(Bp + k0);
        __syncthreads();
        As[lk + 0][lr] = av.x; As[lk + 1][lr] = av.y;
        As[lk + 2][lr] = av.z; As[lk + 3][lr] = av.w;
        Bs[lk + 0][lr] = bv.x; Bs[lk + 1][lr] = bv.y;
        Bs[lk + 2][lr] = bv.z; Bs[lk + 3][lr] = bv.w;
        __syncthreads();
        #pragma unroll
        for (int k = 0; k < BK; k++) {
            float4 a = *(const float4*)&As[k][ty << 2];
            float4 b = *(const float4*)&Bs[k][tx << 2];
            float ar[4] = {a.x, a.y, a.z, a.w};
            float br[4] = {b.x, b.y, b.z, b.w};
            #pragma unroll
            for (int i = 0; i < 4; i++)
                #pragma unroll
                for (int j = 0; j < 4; j++)
                    acc[i][j] = fmaf(ar[i], br[j], acc[i][j]);
        }
    }
    #pragma unroll
    for (int i = 0; i < 4; i++) {
        int row = row0 + (ty << 2) + i;
        int col = col0 + (tx << 2);
        float4 o;
        o.x = acc[i][0] + (bias ? bias[col + 0] : 0.f);
        o.y = acc[i][1] + (bias ? bias[col + 1] : 0.f);
        o.z = acc[i][2] + (bias ? bias[col + 2] : 0.f);
        o.w = acc[i][3] + (bias ? bias[col + 3] : 0.f);
        *(float4*)(C + (size_t)row * ldc + col) = o;
    }
}

// ---------------- fused distance GEMM + rowwise argmin ----------------
// d_k = (|f|^2 + |c_k|^2) - 2*(f.c_k), same fp32 rounding structure as reference.
// argmin with lowest-index tie break (strict <, ascending scan order).
__global__ __launch_bounds__(256) void vq_argmin(
    const float* __restrict__ feat,
    const float* __restrict__ cb,
    const float* __restrict__ rown,
    const float* __restrict__ cnorm,
    int Kcodes,
    int* __restrict__ idx_out,
    float* __restrict__ idxf_out)
{
    __shared__ float As[BK][BM + 4];
    __shared__ float Bs[BK][BN + 4];
    __shared__ float sval[BM][16];
    __shared__ int   sidx[BM][16];
    __shared__ float sbv[BM];
    __shared__ int   sbi[BM];

    int t = threadIdx.x;
    int tx = t & 15, ty = t >> 4;
    int row0 = blockIdx.x * BM;
    if (t < BM) { sbv[t] = 3.4e38f; sbi[t] = 0; }
    int lr = t >> 2;
    int lk = (t & 3) << 2;
    const float* Ap = feat + (size_t)(row0 + lr) * DDIM + lk;

    for (int nc = 0; nc < Kcodes; nc += BN) {
        float acc[4][4] = {};
        const float* Bp = cb + (size_t)(nc + lr) * DDIM + lk;
        for (int k0 = 0; k0 < DDIM; k0 += BK) {
            float4 av = *(const float4*)(Ap + k0);
            float4 bv = *(const float4*)(Bp + k0);
            __syncthreads();
            As[lk + 0][lr] = av.x; As[lk + 1][lr] = av.y;
            As[lk + 2][lr] = av.z; As[lk + 3][lr] = av.w;
            Bs[lk + 0][lr] = bv.x; Bs[lk + 1][lr] = bv.y;
            Bs[lk + 2][lr] = bv.z; Bs[lk + 3][lr] = bv.w;
            __syncthreads();
            #pragma unroll
            for (int k = 0; k < BK; k++) {
                float4 a = *(const float4*)&As[k][ty << 2];
                float4 b = *(const float4*)&Bs[k][tx << 2];
                float ar[4] = {a.x, a.y, a.z, a.w};
                float br[4] = {b.x, b.y, b.z, b.w};
                #pragma unroll
                for (int i = 0; i < 4; i++)
                    #pragma unroll
                    for (int j = 0; j < 4; j++)
                        acc[i][j] = fmaf(ar[i], br[j], acc[i][j]);
            }
        }
        // epilogue: distances + per-thread argmin over its 4 codes
        #pragma unroll
        for (int i = 0; i < 4; i++) {
            int row = row0 + (ty << 2) + i;
            float An = rown[row];
            float best = 3.4e38f;
            int bi = 0;
            #pragma unroll
            for (int j = 0; j < 4; j++) {
                int code = nc + (tx << 2) + j;
                float s = An + cnorm[code];          // fp32 add (matches ref rounding)
                float dd = s - 2.0f * acc[i][j];     // *2 exact, sub rounded once
                if (dd < best) { best = dd; bi = code; }
            }
            sval[(ty << 2) + i][tx] = best;
            sidx[(ty << 2) + i][tx] = bi;
        }
        __syncthreads();
        if (t < BM) {
            float best = sbv[t];
            int bi = sbi[t];
            #pragma unroll
            for (int c = 0; c < 16; c++) {           // ascending code order
                float v = sval[t][c];
                if (v < best) { best = v; bi = sidx[t][c]; }
            }
            sbv[t] = best; sbi[t] = bi;
        }
    }
    __syncthreads();
    if (t < BM) {
        idx_out[row0 + t] = sbi[t];
        idxf_out[row0 + t] = (float)sbi[t];
    }
}

// ---------------- helpers ----------------
__device__ __forceinline__ float blockReduceSum128(float v)
{
    __shared__ float sm[128];
    int t = threadIdx.x;
    sm[t] = v;
    __syncthreads();
    for (int s = 64; s > 0; s >>= 1) {
        if (t < s) sm[t] += sm[t + s];
        __syncthreads();
    }
    float r = sm[0];
    __syncthreads();
    return r;
}

// |row|^2 for each row of X (row length DDIM); one 128-thread block per row
__global__ __launch_bounds__(128) void rownorm(const float* __restrict__ X,
                                               float* __restrict__ out)
{
    int row = blockIdx.x;
    int t = threadIdx.x;
    float4 v = ((const float4*)(X + (size_t)row * DDIM))[t];
    float s = v.x * v.x + v.y * v.y + v.z * v.z + v.w * v.w;
    float tot = blockReduceSum128(s);
    if (t == 0) out[row] = tot;
}

// residual + losses for timbre/expr/detail-stage0; also |resid|^2 per row
__global__ __launch_bounds__(128) void resid_loss(
    const float* __restrict__ tf, const float* __restrict__ ef,
    const float* __restrict__ df,
    const float* __restrict__ tcb, const float* __restrict__ ecb,
    const float* __restrict__ cb0,
    const int* __restrict__ idx,
    float* __restrict__ resid, float* __restrict__ rownR,
    float* __restrict__ lacc)
{
    int n = blockIdx.x;
    int t = threadIdx.x;
    int it = idx[0 * NTOK + n];
    int ie = idx[1 * NTOK + n];
    int i0 = idx[2 * NTOK + n];

    float4 a, c;
    a = ((const float4*)(tf + (size_t)n * DDIM))[t];
    c = ((const float4*)(tcb + (size_t)it * DDIM))[t];
    float dx = c.x - a.x, dy = c.y - a.y, dz = c.z - a.z, dw = c.w - a.w;
    float st = dx * dx + dy * dy + dz * dz + dw * dw;

    a = ((const float4*)(ef + (size_t)n * DDIM))[t];
    c = ((const float4*)(ecb + (size_t)ie * DDIM))[t];
    dx = c.x - a.x; dy = c.y - a.y; dz = c.z - a.z; dw = c.w - a.w;
    float se = dx * dx + dy * dy + dz * dz + dw * dw;

    a = ((const float4*)(df + (size_t)n * DDIM))[t];
    c = ((const float4*)(cb0 + (size_t)i0 * DDIM))[t];
    float4 r;
    r.x = a.x - c.x; r.y = a.y - c.y; r.z = a.z - c.z; r.w = a.w - c.w;
    ((float4*)(resid + (size_t)n * DDIM))[t] = r;
    float sr = r.x * r.x + r.y * r.y + r.z * r.z + r.w * r.w;

    float tt = blockReduceSum128(st);
    if (t == 0) atomicAdd(&lacc[0], tt);
    float te = blockReduceSum128(se);
    if (t == 0) atomicAdd(&lacc[1], te);
    float tr = blockReduceSum128(sr);
    if (t == 0) { atomicAdd(&lacc[2], tr); rownR[n] = tr; }
}

// gather-add of projected codebooks + out bias -> quantized; stage-1 loss
__global__ __launch_bounds__(128) void finalize_out(
    const float* __restrict__ E,        // Et | Ee | E0 | E1 contiguous
    const float* __restrict__ outb,
    const float* __restrict__ cb1,
    const float* __restrict__ resid,
    const int* __restrict__ idx,
    float* __restrict__ qout,
    float* __restrict__ lacc)
{
    int n = blockIdx.x;
    int t = threadIdx.x;
    int it = idx[0 * NTOK + n];
    int ie = idx[1 * NTOK + n];
    int i0 = idx[2 * NTOK + n];
    int i1 = idx[3 * NTOK + n];

    const float4* Et = (const float4*)(E + (size_t)it * DDIM);
    const float4* Ee = (const float4*)(E + (size_t)(KT + ie) * DDIM);
    const float4* E0 = (const float4*)(E + (size_t)(KT + KE + i0) * DDIM);
    const float4* E1 = (const float4*)(E + (size_t)(KT + KE + KD + i1) * DDIM);
    const float4* Bb = (const float4*)outb;

    float4 q;
    float4 v0 = Et[t], v1 = Ee[t], v2 = E0[t], v3 = E1[t], vb = Bb[t];
    q.x = v0.x + v1.x + v2.x + v3.x + vb.x;
    q.y = v0.y + v1.y + v2.y + v3.y + vb.y;
    q.z = v0.z + v1.z + v2.z + v3.z + vb.z;
    q.w = v0.w + v1.w + v2.w + v3.w + vb.w;
    ((float4*)(qout + (size_t)n * DDIM))[t] = q;

    float4 c = ((const float4*)(cb1 + (size_t)i1 * DDIM))[t];
    float4 r = ((const float4*)(resid + (size_t)n * DDIM))[t];
    float dx = c.x - r.x, dy = c.y - r.y, dz = c.z - r.z, dw = c.w - r.w;
    float s1 = dx * dx + dy * dy + dz * dz + dw * dw;
    float ts = blockReduceSum128(s1);
    if (t == 0) atomicAdd(&lacc[3], ts);
}

__global__ void zero_lacc(float* lacc)
{
    if (threadIdx.x < 4) lacc[threadIdx.x] = 0.f;
}

__global__ void write_loss(const float* __restrict__ lacc, float* __restrict__ out)
{
    if (threadIdx.x == 0) {
        float total = lacc[0] + lacc[1] + lacc[2] + lacc[3];
        out[0] = 1.25f * total * (1.0f / ((float)NTOK * (float)DDIM));
    }
}

// ---------------- host ----------------
extern "C" void kernel_launch(void* const* d_in, const int* in_sizes, int n_in,
                              void* d_out, int out_size)
{
    const float* x   = (const float*)d_in[0];
    const float* tW  = (const float*)d_in[1];
    const float* tb  = (const float*)d_in[2];
    const float* eW  = (const float*)d_in[3];
    const float* eb  = (const float*)d_in[4];
    const float* dW  = (const float*)d_in[5];
    const float* db  = (const float*)d_in[6];
    const float* oW  = (const float*)d_in[7];
    const float* ob  = (const float*)d_in[8];
    const float* tcb = (const float*)d_in[9];
    const float* ecb = (const float*)d_in[10];
    const float* cb0 = (const float*)d_in[11];
    const float* cb1 = (const float*)d_in[12];

    float* out = (float*)d_out;
    float* q_out    = out;                               // [NTOK*DDIM]
    float* idxf     = out + (size_t)NTOK * DDIM;         // 4x [NTOK]
    float* loss_out = idxf + (size_t)4 * NTOK;           // [1]

    float *tfeat, *efeat, *dfeat, *resid, *rown, *E, *cn, *lacc;
    int* idx;
    cudaGetSymbolAddress((void**)&tfeat, g_tfeat);
    cudaGetSymbolAddress((void**)&efeat, g_efeat);
    cudaGetSymbolAddress((void**)&dfeat, g_dfeat);
    cudaGetSymbolAddress((void**)&resid, g_resid);
    cudaGetSymbolAddress((void**)&rown,  g_rown);
    cudaGetSymbolAddress((void**)&idx,   g_idx);
    cudaGetSymbolAddress((void**)&E,     g_E);
    cudaGetSymbolAddress((void**)&cn,    g_cn);
    cudaGetSymbolAddress((void**)&lacc,  g_lacc);

    zero_lacc<<<1, 32>>>(lacc);

    // feature linears: feat = x @ W^T + b
    dim3 gfeat(DDIM / BN, NTOK / BM);
    sgemm_bias<<<gfeat, 256>>>(x, DDIM, tW, DDIM, tb, tfeat, DDIM, DDIM);
    sgemm_bias<<<gfeat, 256>>>(x, DDIM, eW, DDIM, eb, efeat, DDIM, DDIM);
    sgemm_bias<<<gfeat, 256>>>(x, DDIM, dW, DDIM, db, dfeat, DDIM, DDIM);

    // row norms of features
    rownorm<<<NTOK, 128>>>(tfeat, rown + 0 * NTOK);
    rownorm<<<NTOK, 128>>>(efeat, rown + 1 * NTOK);
    rownorm<<<NTOK, 128>>>(dfeat, rown + 2 * NTOK);

    // codebook norms
    rownorm<<<KT, 128>>>(tcb, cn + 0);
    rownorm<<<KE, 128>>>(ecb, cn + KT);
    rownorm<<<KD, 128>>>(cb0, cn + KT + KE);
    rownorm<<<KD, 128>>>(cb1, cn + KT + KE + KD);

    // projected codebooks: E = cb @ oW_slice^T  (out_W is [512,1536] row-major)
    dim3 gEt(DDIM / BN, KT / BM), gEe(DDIM / BN, KE / BM), gEd(DDIM / BN, KD / BM);
    sgemm_bias<<<gEt, 256>>>(tcb, DDIM, oW + 0,        3 * DDIM, nullptr,
                             E + (size_t)0 * DDIM,              DDIM, DDIM);
    sgemm_bias<<<gEe, 256>>>(ecb, DDIM, oW + DDIM,     3 * DDIM, nullptr,
                             E + (size_t)KT * DDIM,             DDIM, DDIM);
    sgemm_bias<<<gEd, 256>>>(cb0, DDIM, oW + 2 * DDIM, 3 * DDIM, nullptr,
                             E + (size_t)(KT + KE) * DDIM,      DDIM, DDIM);
    sgemm_bias<<<gEd, 256>>>(cb1, DDIM, oW + 2 * DDIM, 3 * DDIM, nullptr,
                             E + (size_t)(KT + KE + KD) * DDIM, DDIM, DDIM);

    // VQ stages
    vq_argmin<<<NTOK / BM, 256>>>(tfeat, tcb, rown + 0 * NTOK, cn + 0, KT,
                                  idx + 0 * NTOK, idxf + 0 * NTOK);
    vq_argmin<<<NTOK / BM, 256>>>(efeat, ecb, rown + 1 * NTOK, cn + KT, KE,
                                  idx + 1 * NTOK, idxf + 1 * NTOK);
    vq_argmin<<<NTOK / BM, 256>>>(dfeat, cb0, rown + 2 * NTOK, cn + KT + KE, KD,
                                  idx + 2 * NTOK, idxf + 2 * NTOK);

    // residual + losses for first three quantizers
    resid_loss<<<NTOK, 128>>>(tfeat, efeat, dfeat, tcb, ecb, cb0, idx,
                              resid, rown + 3 * NTOK, lacc);

    // second detail stage on residual
    vq_argmin<<<NTOK / BM, 256>>>(resid, cb1, rown + 3 * NTOK,
                                  cn + KT + KE + KD, KD,
                                  idx + 3 * NTOK, idxf + 3 * NTOK);

    // gather-add projected codebooks -> quantized output; stage-1 loss
    finalize_out<<<NTOK, 128>>>(E, ob, cb1, resid, idx, q_out, lacc);

    write_loss<<<1, 32>>>(lacc, loss_out);
}

// round 3
// speedup vs baseline: 1.1287x; 1.1287x over previous
#include <cuda_runtime.h>

#define NTOK 65536
#define DDIM 512
#define KT 512
#define KE 256
#define KD 512
#define KTOT (KT + KE + KD + KD)

// ---------------- scratch (device globals; no runtime alloc) ----------------
__device__ float g_tfeat[(size_t)NTOK * DDIM];
__device__ float g_efeat[(size_t)NTOK * DDIM];
__device__ float g_dfeat[(size_t)NTOK * DDIM];
__device__ float g_resid[(size_t)NTOK * DDIM];
__device__ float g_rown[4 * NTOK];          // |f|^2 per token per stage
__device__ int   g_idx[4 * NTOK];           // argmin indices per stage
__device__ float g_E[(size_t)KTOT * DDIM];  // projected codebooks Et,Ee,E0,E1
__device__ float g_cn[KTOT];                // |c|^2 per code
__device__ float g_lacc[4];                 // loss sum accumulators

// ---------------- packed fp32x2 helpers (Blackwell f32x2 pipe) ----------------
#define FMA2(d, a, b) asm("fma.rn.f32x2 %0, %1, %2, %0;" : "+l"(d) : "l"(a), "l"(b))
#define PACK2(d, x, y) asm("mov.b64 %0, {%1, %2};" : "=l"(d) : "f"(x), "f"(y))
#define UNPACK2(x, y, d) asm("mov.b64 {%0, %1}, %2;" : "=f"(x), "=f"(y) : "l"(d))

// ---------------- 128x128x16 tile SGEMM core --------------------------------
#define TBM 128
#define TBN 128
#define TBK 16
#define PADW 132                       // 128 + 4 pad (bank spread for sts)
#define STAGE (2 * TBK * PADW)         // As + Bs for one stage (floats)
#define SMEMF (2 * STAGE)              // double buffered

__device__ __forceinline__ void sts_tile(float* s, int str, int sto,
                                         float4 a0, float4 a1,
                                         float4 b0, float4 b1)
{
    float* As_ = s;
    float* Bs_ = s + TBK * PADW;
    As_[(sto + 0) * PADW + str] = a0.x;
    As_[(sto + 1) * PADW + str] = a0.y;
    As_[(sto + 2) * PADW + str] = a0.z;
    As_[(sto + 3) * PADW + str] = a0.w;
    As_[(sto + 0) * PADW + str + 64] = a1.x;
    As_[(sto + 1) * PADW + str + 64] = a1.y;
    As_[(sto + 2) * PADW + str + 64] = a1.z;
    As_[(sto + 3) * PADW + str + 64] = a1.w;
    Bs_[(sto + 0) * PADW + str] = b0.x;
    Bs_[(sto + 1) * PADW + str] = b0.y;
    Bs_[(sto + 2) * PADW + str] = b0.z;
    Bs_[(sto + 3) * PADW + str] = b0.w;
    Bs_[(sto + 0) * PADW + str + 64] = b1.x;
    Bs_[(sto + 1) * PADW + str + 64] = b1.y;
    Bs_[(sto + 2) * PADW + str + 64] = b1.z;
    Bs_[(sto + 3) * PADW + str + 64] = b1.w;
}

__device__ __forceinline__ void mm_tile(const float* s, int tm, int tn,
                                        unsigned long long acc[8][4])
{
    const float* As_ = s;
    const float* Bs_ = s + TBK * PADW;
    #pragma unroll
    for (int k = 0; k < TBK; k++) {
        const float* ap = &As_[k * PADW + tm * 8];
        const float* bp = &Bs_[k * PADW + tn * 8];
        float4 a0 = *(const float4*)ap;
        float4 a1 = *(const float4*)(ap + 4);
        float4 b0 = *(const float4*)bp;
        float4 b1 = *(const float4*)(bp + 4);
        unsigned long long bb0, bb1, bb2, bb3;
        PACK2(bb0, b0.x, b0.y); PACK2(bb1, b0.z, b0.w);
        PACK2(bb2, b1.x, b1.y); PACK2(bb3, b1.z, b1.w);
        float av[8] = {a0.x, a0.y, a0.z, a0.w, a1.x, a1.y, a1.z, a1.w};
        #pragma unroll
        for (int i = 0; i < 8; i++) {
            unsigned long long aa;
            PACK2(aa, av[i], av[i]);
            FMA2(acc[i][0], aa, bb0);
            FMA2(acc[i][1], aa, bb1);
            FMA2(acc[i][2], aa, bb2);
            FMA2(acc[i][3], aa, bb3);
        }
    }
}

// C[m][n] = sum_k A[m*lda+k] * B[n*ldb+k] (+ bias[n])
__global__ __launch_bounds__(256) void sgemm128(
    const float* __restrict__ A, int lda,
    const float* __restrict__ B, int ldb,
    const float* __restrict__ bias,
    float* __restrict__ C, int ldc, int Kd)
{
    __shared__ float smem[SMEMF];
    int t = threadIdx.x;
    int tm = t >> 4, tn = t & 15;
    int row0 = blockIdx.y * TBM;
    int col0 = blockIdx.x * TBN;
    int str = t >> 2;
    int sto = (t & 3) * 4;

    const float* Ap = A + (size_t)(row0 + str) * lda + sto;
    const float* Bp = B + (size_t)(col0 + str) * ldb + sto;

    unsigned long long acc[8][4] = {};

    int nt = Kd / TBK;
    // prologue: tile 0
    {
        float4 a0 = *(const float4*)(Ap);
        float4 a1 = *(const float4*)(Ap + (size_t)64 * lda);
        float4 b0 = *(const float4*)(Bp);
        float4 b1 = *(const float4*)(Bp + (size_t)64 * ldb);
        sts_tile(smem, str, sto, a0, a1, b0, b1);
    }
    __syncthreads();
    for (int kt = 0; kt < nt; kt++) {
        float4 a0, a1, b0, b1;
        if (kt + 1 < nt) {
            int ko = (kt + 1) * TBK;
            a0 = *(const float4*)(Ap + ko);
            a1 = *(const float4*)(Ap + (size_t)64 * lda + ko);
            b0 = *(const float4*)(Bp + ko);
            b1 = *(const float4*)(Bp + (size_t)64 * ldb + ko);
        }
        mm_tile(smem + (kt & 1) * STAGE, tm, tn, acc);
        if (kt + 1 < nt)
            sts_tile(smem + ((kt + 1) & 1) * STAGE, str, sto, a0, a1, b0, b1);
        __syncthreads();
    }

    #pragma unroll
    for (int i = 0; i < 8; i++) {
        int row = row0 + tm * 8 + i;
        int col = col0 + tn * 8;
        float o[8];
        UNPACK2(o[0], o[1], acc[i][0]);
        UNPACK2(o[2], o[3], acc[i][1]);
        UNPACK2(o[4], o[5], acc[i][2]);
        UNPACK2(o[6], o[7], acc[i][3]);
        if (bias) {
            #pragma unroll
            for (int j = 0; j < 8; j++) o[j] += bias[col + j];
        }
        float4 w0 = {o[0], o[1], o[2], o[3]};
        float4 w1 = {o[4], o[5], o[6], o[7]};
        *(float4*)(C + (size_t)row * ldc + col) = w0;
        *(float4*)(C + (size_t)row * ldc + col + 4) = w1;
    }
}

// ---------------- fused distance GEMM + rowwise argmin ----------------
// d = (|f|^2 + |c|^2) - 2*(f.c); lowest-index tie break.
__global__ __launch_bounds__(256) void vq_argmin(
    const float* __restrict__ feat,
    const float* __restrict__ cb,
    const float* __restrict__ rown,
    const float* __restrict__ cnorm,
    int Kcodes,
    int* __restrict__ idx_out,
    float* __restrict__ idxf_out)
{
    __shared__ float smem[SMEMF];
    int t = threadIdx.x;
    int tm = t >> 4, tn = t & 15;
    int row0 = blockIdx.x * TBM;
    int str = t >> 2;
    int sto = (t & 3) * 4;

    const float* Ap = feat + (size_t)(row0 + str) * DDIM + sto;

    float bestv[8];
    int bidx[8];
    #pragma unroll
    for (int i = 0; i < 8; i++) { bestv[i] = 3.4e38f; bidx[i] = 0; }

    const int nt = DDIM / TBK;
    for (int nc = 0; nc < Kcodes; nc += TBN) {
        const float* Bp = cb + (size_t)(nc + str) * DDIM + sto;
        unsigned long long acc[8][4] = {};
        {
            float4 a0 = *(const float4*)(Ap);
            float4 a1 = *(const float4*)(Ap + (size_t)64 * DDIM);
            float4 b0 = *(const float4*)(Bp);
            float4 b1 = *(const float4*)(Bp + (size_t)64 * DDIM);
            sts_tile(smem, str, sto, a0, a1, b0, b1);
        }
        __syncthreads();
        for (int kt = 0; kt < nt; kt++) {
            float4 a0, a1, b0, b1;
            if (kt + 1 < nt) {
                int ko = (kt + 1) * TBK;
                a0 = *(const float4*)(Ap + ko);
                a1 = *(const float4*)(Ap + (size_t)64 * DDIM + ko);
                b0 = *(const float4*)(Bp + ko);
                b1 = *(const float4*)(Bp + (size_t)64 * DDIM + ko);
            }
            mm_tile(smem + (kt & 1) * STAGE, tm, tn, acc);
            if (kt + 1 < nt)
                sts_tile(smem + ((kt + 1) & 1) * STAGE, str, sto, a0, a1, b0, b1);
            __syncthreads();
        }
        // epilogue: distances for this 128-code chunk
        float cw[8];
        #pragma unroll
        for (int j = 0; j < 8; j++) cw[j] = cnorm[nc + tn * 8 + j];
        #pragma unroll
        for (int i = 0; i < 8; i++) {
            float An = rown[row0 + tm * 8 + i];
            float s[8];
            UNPACK2(s[0], s[1], acc[i][0]);
            UNPACK2(s[2], s[3], acc[i][1]);
            UNPACK2(s[4], s[5], acc[i][2]);
            UNPACK2(s[6], s[7], acc[i][3]);
            #pragma unroll
            for (int j = 0; j < 8; j++) {
                float d = (An + cw[j]) - 2.0f * s[j];
                if (d < bestv[i]) { bestv[i] = d; bidx[i] = nc + tn * 8 + j; }
            }
        }
    }

    // cross-thread reduce: alias smem (safe: loop ends with __syncthreads)
    float* sval = smem;                       // [128][16]
    int*   sidx = (int*)(smem + 2048);        // [128][16]
    #pragma unroll
    for (int i = 0; i < 8; i++) {
        sval[(tm * 8 + i) * 16 + tn] = bestv[i];
        sidx[(tm * 8 + i) * 16 + tn] = bidx[i];
    }
    __syncthreads();
    if (t < TBM) {
        float bv = 3.4e38f;
        int bi = 0x7fffffff;
        #pragma unroll
        for (int c = 0; c < 16; c++) {
            float v = sval[t * 16 + c];
            int id = sidx[t * 16 + c];
            if (v < bv || (v == bv && id < bi)) { bv = v; bi = id; }
        }
        idx_out[row0 + t] = bi;
        idxf_out[row0 + t] = (float)bi;
    }
}

// ---------------- helpers ----------------
__device__ __forceinline__ float blockReduceSum128(float v)
{
    __shared__ float sm[128];
    int t = threadIdx.x;
    sm[t] = v;
    __syncthreads();
    for (int s = 64; s > 0; s >>= 1) {
        if (t < s) sm[t] += sm[t + s];
        __syncthreads();
    }
    float r = sm[0];
    __syncthreads();
    return r;
}

__global__ __launch_bounds__(128) void rownorm(const float* __restrict__ X,
                                               float* __restrict__ out)
{
    int row = blockIdx.x;
    int t = threadIdx.x;
    float4 v = ((const float4*)(X + (size_t)row * DDIM))[t];
    float s = v.x * v.x + v.y * v.y + v.z * v.z + v.w * v.w;
    float tot = blockReduceSum128(s);
    if (t == 0) out[row] = tot;
}

__global__ __launch_bounds__(128) void resid_loss(
    const float* __restrict__ tf, const float* __restrict__ ef,
    const float* __restrict__ df,
    const float* __restrict__ tcb, const float* __restrict__ ecb,
    const float* __restrict__ cb0,
    const int* __restrict__ idx,
    float* __restrict__ resid, float* __restrict__ rownR,
    float* __restrict__ lacc)
{
    int n = blockIdx.x;
    int t = threadIdx.x;
    int it = idx[0 * NTOK + n];
    int ie = idx[1 * NTOK + n];
    int i0 = idx[2 * NTOK + n];

    float4 a, c;
    a = ((const float4*)(tf + (size_t)n * DDIM))[t];
    c = ((const float4*)(tcb + (size_t)it * DDIM))[t];
    float dx = c.x - a.x, dy = c.y - a.y, dz = c.z - a.z, dw = c.w - a.w;
    float st = dx * dx + dy * dy + dz * dz + dw * dw;

    a = ((const float4*)(ef + (size_t)n * DDIM))[t];
    c = ((const float4*)(ecb + (size_t)ie * DDIM))[t];
    dx = c.x - a.x; dy = c.y - a.y; dz = c.z - a.z; dw = c.w - a.w;
    float se = dx * dx + dy * dy + dz * dz + dw * dw;

    a = ((const float4*)(df + (size_t)n * DDIM))[t];
    c = ((const float4*)(cb0 + (size_t)i0 * DDIM))[t];
    float4 r;
    r.x = a.x - c.x; r.y = a.y - c.y; r.z = a.z - c.z; r.w = a.w - c.w;
    ((float4*)(resid + (size_t)n * DDIM))[t] = r;
    float sr = r.x * r.x + r.y * r.y + r.z * r.z + r.w * r.w;

    float tt = blockReduceSum128(st);
    if (t == 0) atomicAdd(&lacc[0], tt);
    float te = blockReduceSum128(se);
    if (t == 0) atomicAdd(&lacc[1], te);
    float tr = blockReduceSum128(sr);
    if (t == 0) { atomicAdd(&lacc[2], tr); rownR[n] = tr; }
}

__global__ __launch_bounds__(128) void finalize_out(
    const float* __restrict__ E,
    const float* __restrict__ outb,
    const float* __restrict__ cb1,
    const float* __restrict__ resid,
    const int* __restrict__ idx,
    float* __restrict__ qout,
    float* __restrict__ lacc)
{
    int n = blockIdx.x;
    int t = threadIdx.x;
    int it = idx[0 * NTOK + n];
    int ie = idx[1 * NTOK + n];
    int i0 = idx[2 * NTOK + n];
    int i1 = idx[3 * NTOK + n];

    const float4* Et = (const float4*)(E + (size_t)it * DDIM);
    const float4* Ee = (const float4*)(E + (size_t)(KT + ie) * DDIM);
    const float4* E0 = (const float4*)(E + (size_t)(KT + KE + i0) * DDIM);
    const float4* E1 = (const float4*)(E + (size_t)(KT + KE + KD + i1) * DDIM);
    const float4* Bb = (const float4*)outb;

    float4 q;
    float4 v0 = Et[t], v1 = Ee[t], v2 = E0[t], v3 = E1[t], vb = Bb[t];
    q.x = v0.x + v1.x + v2.x + v3.x + vb.x;
    q.y = v0.y + v1.y + v2.y + v3.y + vb.y;
    q.z = v0.z + v1.z + v2.z + v3.z + vb.z;
    q.w = v0.w + v1.w + v2.w + v3.w + vb.w;
    ((float4*)(qout + (size_t)n * DDIM))[t] = q;

    float4 c = ((const float4*)(cb1 + (size_t)i1 * DDIM))[t];
    float4 r = ((const float4*)(resid + (size_t)n * DDIM))[t];
    float dx = c.x - r.x, dy = c.y - r.y, dz = c.z - r.z, dw = c.w - r.w;
    float s1 = dx * dx + dy * dy + dz * dz + dw * dw;
    float ts = blockReduceSum128(s1);
    if (t == 0) atomicAdd(&lacc[3], ts);
}

__global__ void zero_lacc(float* lacc)
{
    if (threadIdx.x < 4) lacc[threadIdx.x] = 0.f;
}

__global__ void write_loss(const float* __restrict__ lacc, float* __restrict__ out)
{
    if (threadIdx.x == 0) {
        float total = lacc[0] + lacc[1] + lacc[2] + lacc[3];
        out[0] = 1.25f * total * (1.0f / ((float)NTOK * (float)DDIM));
    }
}

// ---------------- host ----------------
extern "C" void kernel_launch(void* const* d_in, const int* in_sizes, int n_in,
                              void* d_out, int out_size)
{
    const float* x   = (const float*)d_in[0];
    const float* tW  = (const float*)d_in[1];
    const float* tb  = (const float*)d_in[2];
    const float* eW  = (const float*)d_in[3];
    const float* eb  = (const float*)d_in[4];
    const float* dW  = (const float*)d_in[5];
    const float* db  = (const float*)d_in[6];
    const float* oW  = (const float*)d_in[7];
    const float* ob  = (const float*)d_in[8];
    const float* tcb = (const float*)d_in[9];
    const float* ecb = (const float*)d_in[10];
    const float* cb0 = (const float*)d_in[11];
    const float* cb1 = (const float*)d_in[12];

    float* out = (float*)d_out;
    float* q_out    = out;                               // [NTOK*DDIM]
    float* idxf     = out + (size_t)NTOK * DDIM;         // 4x [NTOK]
    float* loss_out = idxf + (size_t)4 * NTOK;           // [1]

    float *tfeat, *efeat, *dfeat, *resid, *rown, *E, *cn, *lacc;
    int* idx;
    cudaGetSymbolAddress((void**)&tfeat, g_tfeat);
    cudaGetSymbolAddress((void**)&efeat, g_efeat);
    cudaGetSymbolAddress((void**)&dfeat, g_dfeat);
    cudaGetSymbolAddress((void**)&resid, g_resid);
    cudaGetSymbolAddress((void**)&rown,  g_rown);
    cudaGetSymbolAddress((void**)&idx,   g_idx);
    cudaGetSymbolAddress((void**)&E,     g_E);
    cudaGetSymbolAddress((void**)&cn,    g_cn);
    cudaGetSymbolAddress((void**)&lacc,  g_lacc);

    zero_lacc<<<1, 32>>>(lacc);

    // feature linears: feat = x @ W^T + b
    dim3 gfeat(DDIM / TBN, NTOK / TBM);
    sgemm128<<<gfeat, 256>>>(x, DDIM, tW, DDIM, tb, tfeat, DDIM, DDIM);
    sgemm128<<<gfeat, 256>>>(x, DDIM, eW, DDIM, eb, efeat, DDIM, DDIM);
    sgemm128<<<gfeat, 256>>>(x, DDIM, dW, DDIM, db, dfeat, DDIM, DDIM);

    // row norms of features
    rownorm<<<NTOK, 128>>>(tfeat, rown + 0 * NTOK);
    rownorm<<<NTOK, 128>>>(efeat, rown + 1 * NTOK);
    rownorm<<<NTOK, 128>>>(dfeat, rown + 2 * NTOK);

    // codebook norms
    rownorm<<<KT, 128>>>(tcb, cn + 0);
    rownorm<<<KE, 128>>>(ecb, cn + KT);
    rownorm<<<KD, 128>>>(cb0, cn + KT + KE);
    rownorm<<<KD, 128>>>(cb1, cn + KT + KE + KD);

    // projected codebooks: E = cb @ oW_slice^T  (out_W is [512,1536] row-major)
    dim3 gEt(DDIM / TBN, KT / TBM), gEe(DDIM / TBN, KE / TBM), gEd(DDIM / TBN, KD / TBM);
    sgemm128<<<gEt, 256>>>(tcb, DDIM, oW + 0,        3 * DDIM, nullptr,
                           E + (size_t)0 * DDIM,              DDIM, DDIM);
    sgemm128<<<gEe, 256>>>(ecb, DDIM, oW + DDIM,     3 * DDIM, nullptr,
                           E + (size_t)KT * DDIM,             DDIM, DDIM);
    sgemm128<<<gEd, 256>>>(cb0, DDIM, oW + 2 * DDIM, 3 * DDIM, nullptr,
                           E + (size_t)(KT + KE) * DDIM,      DDIM, DDIM);
    sgemm128<<<gEd, 256>>>(cb1, DDIM, oW + 2 * DDIM, 3 * DDIM, nullptr,
                           E + (size_t)(KT + KE + KD) * DDIM, DDIM, DDIM);

    // VQ stages
    vq_argmin<<<NTOK / TBM, 256>>>(tfeat, tcb, rown + 0 * NTOK, cn + 0, KT,
                                   idx + 0 * NTOK, idxf + 0 * NTOK);
    vq_argmin<<<NTOK / TBM, 256>>>(efeat, ecb, rown + 1 * NTOK, cn + KT, KE,
                                   idx + 1 * NTOK, idxf + 1 * NTOK);
    vq_argmin<<<NTOK / TBM, 256>>>(dfeat, cb0, rown + 2 * NTOK, cn + KT + KE, KD,
                                   idx + 2 * NTOK, idxf + 2 * NTOK);

    // residual + losses for first three quantizers
    resid_loss<<<NTOK, 128>>>(tfeat, efeat, dfeat, tcb, ecb, cb0, idx,
                              resid, rown + 3 * NTOK, lacc);

    // second detail stage on residual
    vq_argmin<<<NTOK / TBM, 256>>>(resid, cb1, rown + 3 * NTOK,
                                   cn + KT + KE + KD, KD,
                                   idx + 3 * NTOK, idxf + 3 * NTOK);

    // gather-add projected codebooks -> quantized output; stage-1 loss
    finalize_out<<<NTOK, 128>>>(E, ob, cb1, resid, idx, q_out, lacc);

    write_loss<<<1, 32>>>(lacc, loss_out);
}

// round 4
// speedup vs baseline: 1.4481x; 1.2830x over previous
#include <cuda_runtime.h>

#define NTOK 65536
#define DDIM 512
#define KT 512
#define KE 256
#define KD 512
#define KTOT (KT + KE + KD + KD)

// ---------------- scratch (device globals; no runtime alloc) ----------------
__device__ float g_tfeat[(size_t)NTOK * DDIM];
__device__ float g_efeat[(size_t)NTOK * DDIM];
__device__ float g_dfeat[(size_t)NTOK * DDIM];
__device__ float g_resid[(size_t)NTOK * DDIM];
__device__ float g_rown[4 * NTOK];          // |f|^2 per token per stage
__device__ int   g_idx[4 * NTOK];           // argmin indices per stage
__device__ float g_E[(size_t)KTOT * DDIM];  // projected codebooks Et,Ee,E0,E1
__device__ float g_cn[KTOT];                // |c|^2 per code
__device__ float g_lacc[4];                 // loss sum accumulators

// ---------------- packed fp32x2 helpers ----------------
#define FMA2(d, a, b) asm("fma.rn.f32x2 %0, %1, %2, %0;" : "+l"(d) : "l"(a), "l"(b))
#define PACK2(d, x, y) asm("mov.b64 %0, {%1, %2};" : "=l"(d) : "f"(x), "f"(y))
#define UNPACK2(x, y, d) asm("mov.b64 {%0, %1}, %2;" : "=f"(x), "=f"(y) : "l"(d))

// ---------------- 128x128x16 tile, 128 threads, 16x8 micro-tile --------------
#define TBM 128
#define TBN 128
#define TBK 16
#define PADW 132
#define STAGE (2 * TBK * PADW)   // As + Bs, one stage (floats)
#define SMEMF (2 * STAGE)        // double buffered

__device__ __forceinline__ void ldg_tile(const float* Ap, const float* Bp,
                                         int lda, int ldb, int ko,
                                         float4 a[4], float4 b[4])
{
    #pragma unroll
    for (int p = 0; p < 4; p++) {
        a[p] = *(const float4*)(Ap + (size_t)(32 * p) * lda + ko);
        b[p] = *(const float4*)(Bp + (size_t)(32 * p) * ldb + ko);
    }
}

__device__ __forceinline__ void sts_tile(float* s, int str, int sto,
                                         const float4 a[4], const float4 b[4])
{
    float* As_ = s;
    float* Bs_ = s + TBK * PADW;
    #pragma unroll
    for (int p = 0; p < 4; p++) {
        int r = str + 32 * p;
        As_[(sto + 0) * PADW + r] = a[p].x;
        As_[(sto + 1) * PADW + r] = a[p].y;
        As_[(sto + 2) * PADW + r] = a[p].z;
        As_[(sto + 3) * PADW + r] = a[p].w;
        Bs_[(sto + 0) * PADW + r] = b[p].x;
        Bs_[(sto + 1) * PADW + r] = b[p].y;
        Bs_[(sto + 2) * PADW + r] = b[p].z;
        Bs_[(sto + 3) * PADW + r] = b[p].w;
    }
}

// acc[ip][j]: row-pair ip (rows tm*16+2ip, +2ip+1) x col j (tn*8+j)
__device__ __forceinline__ void mm_tile(const float* s, int tm, int tn,
                                        unsigned long long acc[8][8])
{
    const float* As_ = s;
    const float* Bs_ = s + TBK * PADW;
    #pragma unroll
    for (int k = 0; k < TBK; k++) {
        const float* ap = &As_[k * PADW + tm * 16];
        const float* bp = &Bs_[k * PADW + tn * 8];
        float4 a0 = *(const float4*)ap;
        float4 a1 = *(const float4*)(ap + 4);
        float4 a2 = *(const float4*)(ap + 8);
        float4 a3 = *(const float4*)(ap + 12);
        float4 b0 = *(const float4*)bp;
        float4 b1 = *(const float4*)(bp + 4);
        unsigned long long ap8[8];
        PACK2(ap8[0], a0.x, a0.y); PACK2(ap8[1], a0.z, a0.w);
        PACK2(ap8[2], a1.x, a1.y); PACK2(ap8[3], a1.z, a1.w);
        PACK2(ap8[4], a2.x, a2.y); PACK2(ap8[5], a2.z, a2.w);
        PACK2(ap8[6], a3.x, a3.y); PACK2(ap8[7], a3.z, a3.w);
        float bv[8] = {b0.x, b0.y, b0.z, b0.w, b1.x, b1.y, b1.z, b1.w};
        #pragma unroll
        for (int j = 0; j < 8; j++) {
            unsigned long long bb;
            PACK2(bb, bv[j], bv[j]);
            #pragma unroll
            for (int i = 0; i < 8; i++)
                FMA2(acc[i][j], ap8[i], bb);
        }
    }
}

// C[m][n] = sum_k A[m*lda+k]*B[n*ldb+k] (+ bias[n]); block tile at (row0,col0)
__device__ __forceinline__ void gemm_block(
    const float* A, int lda, const float* B, int ldb,
    const float* bias, float* C, int ldc, int Kd,
    int row0, int col0, float* smem)
{
    int t = threadIdx.x;
    int tm = t >> 4, tn = t & 15;
    int str = t >> 2, sto = (t & 3) * 4;
    const float* Ap = A + (size_t)(row0 + str) * lda + sto;
    const float* Bp = B + (size_t)(col0 + str) * ldb + sto;

    unsigned long long acc[8][8] = {};
    float4 ar[4], br[4];
    ldg_tile(Ap, Bp, lda, ldb, 0, ar, br);
    sts_tile(smem, str, sto, ar, br);
    __syncthreads();
    int nt = Kd / TBK;
    for (int kt = 0; kt < nt; kt++) {
        if (kt + 1 < nt) ldg_tile(Ap, Bp, lda, ldb, (kt + 1) * TBK, ar, br);
        mm_tile(smem + (kt & 1) * STAGE, tm, tn, acc);
        if (kt + 1 < nt) sts_tile(smem + ((kt + 1) & 1) * STAGE, str, sto, ar, br);
        __syncthreads();
    }
    #pragma unroll
    for (int ip = 0; ip < 8; ip++) {
        float lo[8], hi[8];
        #pragma unroll
        for (int j = 0; j < 8; j++) UNPACK2(lo[j], hi[j], acc[ip][j]);
        int r0 = row0 + tm * 16 + 2 * ip;
        int c0 = col0 + tn * 8;
        if (bias) {
            #pragma unroll
            for (int j = 0; j < 8; j++) {
                float bb = bias[c0 + j];
                lo[j] += bb; hi[j] += bb;
            }
        }
        float4 w0 = {lo[0], lo[1], lo[2], lo[3]};
        float4 w1 = {lo[4], lo[5], lo[6], lo[7]};
        float4 w2 = {hi[0], hi[1], hi[2], hi[3]};
        float4 w3 = {hi[4], hi[5], hi[6], hi[7]};
        *(float4*)(C + (size_t)r0 * ldc + c0) = w0;
        *(float4*)(C + (size_t)r0 * ldc + c0 + 4) = w1;
        *(float4*)(C + (size_t)(r0 + 1) * ldc + c0) = w2;
        *(float4*)(C + (size_t)(r0 + 1) * ldc + c0 + 4) = w3;
    }
}

// fused 3 feature linears: z selects (W, b, out)
__global__ __launch_bounds__(128, 2) void feat3_gemm(
    const float* __restrict__ x,
    const float* __restrict__ tW, const float* __restrict__ tb,
    const float* __restrict__ eW, const float* __restrict__ eb,
    const float* __restrict__ dW, const float* __restrict__ db,
    float* __restrict__ tf, float* __restrict__ ef, float* __restrict__ df)
{
    __shared__ float smem[SMEMF];
    int z = blockIdx.z;
    const float* W = (z == 0) ? tW : (z == 1) ? eW : dW;
    const float* b = (z == 0) ? tb : (z == 1) ? eb : db;
    float* C = (z == 0) ? tf : (z == 1) ? ef : df;
    gemm_block(x, DDIM, W, DDIM, b, C, DDIM, DDIM,
               blockIdx.y * TBM, blockIdx.x * TBN, smem);
}

// generic (used for the small E-projection GEMMs)
__global__ __launch_bounds__(128, 2) void sgemm_k(
    const float* __restrict__ A, int lda,
    const float* __restrict__ B, int ldb,
    const float* __restrict__ bias,
    float* __restrict__ C, int ldc, int Kd)
{
    __shared__ float smem[SMEMF];
    gemm_block(A, lda, B, ldb, bias, C, ldc, Kd,
               blockIdx.y * TBM, blockIdx.x * TBN, smem);
}

// ---------------- fused distance GEMM + rowwise argmin ----------------
__device__ __forceinline__ void vq_block(
    const float* feat, const float* cb, const float* rown_,
    const float* cnorm, int Kcodes,
    int* idx_out, float* idxf_out, int row0, float* smem)
{
    int t = threadIdx.x;
    int tm = t >> 4, tn = t & 15;
    int str = t >> 2, sto = (t & 3) * 4;
    const float* Ap = feat + (size_t)(row0 + str) * DDIM + sto;

    float bestv[16];
    int bidx[16];
    #pragma unroll
    for (int i = 0; i < 16; i++) { bestv[i] = 3.4e38f; bidx[i] = 0; }

    const int nt = DDIM / TBK;
    for (int nc = 0; nc < Kcodes; nc += TBN) {
        const float* Bp = cb + (size_t)(nc + str) * DDIM + sto;
        unsigned long long acc[8][8] = {};
        float4 ar[4], br[4];
        ldg_tile(Ap, Bp, DDIM, DDIM, 0, ar, br);
        sts_tile(smem, str, sto, ar, br);
        __syncthreads();
        for (int kt = 0; kt < nt; kt++) {
            if (kt + 1 < nt) ldg_tile(Ap, Bp, DDIM, DDIM, (kt + 1) * TBK, ar, br);
            mm_tile(smem + (kt & 1) * STAGE, tm, tn, acc);
            if (kt + 1 < nt) sts_tile(smem + ((kt + 1) & 1) * STAGE, str, sto, ar, br);
            __syncthreads();
        }
        float cw[8];
        #pragma unroll
        for (int j = 0; j < 8; j++) cw[j] = cnorm[nc + tn * 8 + j];
        #pragma unroll
        for (int ip = 0; ip < 8; ip++) {
            float lo[8], hi[8];
            #pragma unroll
            for (int j = 0; j < 8; j++) UNPACK2(lo[j], hi[j], acc[ip][j]);
            float An0 = rown_[row0 + tm * 16 + 2 * ip];
            float An1 = rown_[row0 + tm * 16 + 2 * ip + 1];
            #pragma unroll
            for (int j = 0; j < 8; j++) {
                int code = nc + tn * 8 + j;
                float d0 = (An0 + cw[j]) - 2.0f * lo[j];
                if (d0 < bestv[2 * ip]) { bestv[2 * ip] = d0; bidx[2 * ip] = code; }
                float d1 = (An1 + cw[j]) - 2.0f * hi[j];
                if (d1 < bestv[2 * ip + 1]) { bestv[2 * ip + 1] = d1; bidx[2 * ip + 1] = code; }
            }
        }
    }

    // cross-thread reduce (alias smem; safe after loop-final barrier)
    float* sval = smem;                 // [128][16]
    int*   sidx = (int*)(smem + 2048);  // [128][16]
    #pragma unroll
    for (int i = 0; i < 16; i++) {
        sval[(tm * 16 + i) * 16 + tn] = bestv[i];
        sidx[(tm * 16 + i) * 16 + tn] = bidx[i];
    }
    __syncthreads();
    if (t < TBM) {
        float bv = 3.4e38f;
        int bi = 0x7fffffff;
        #pragma unroll
        for (int c = 0; c < 16; c++) {
            float v = sval[t * 16 + c];
            int id = sidx[t * 16 + c];
            if (v < bv || (v == bv && id < bi)) { bv = v; bi = id; }
        }
        idx_out[row0 + t] = bi;
        idxf_out[row0 + t] = (float)bi;
    }
}

// fused first-3 VQ stages (y selects stage)
__global__ __launch_bounds__(128, 2) void vq3(
    const float* __restrict__ tf, const float* __restrict__ ef,
    const float* __restrict__ df,
    const float* __restrict__ tcb, const float* __restrict__ ecb,
    const float* __restrict__ cb0,
    const float* __restrict__ rown_, const float* __restrict__ cn_,
    int* __restrict__ idx_, float* __restrict__ idxf_)
{
    __shared__ float smem[SMEMF];
    int s = blockIdx.y;
    const float* feat = (s == 0) ? tf : (s == 1) ? ef : df;
    const float* cb   = (s == 0) ? tcb : (s == 1) ? ecb : cb0;
    const float* rn   = rown_ + s * NTOK;
    const float* cn   = (s == 0) ? cn_ : (s == 1) ? (cn_ + KT) : (cn_ + KT + KE);
    int Kc            = (s == 1) ? KE : KT;
    vq_block(feat, cb, rn, cn, Kc, idx_ + s * NTOK, idxf_ + s * NTOK,
             blockIdx.x * TBM, smem);
}

__global__ __launch_bounds__(128, 2) void vq1(
    const float* __restrict__ feat, const float* __restrict__ cb,
    const float* __restrict__ rown_, const float* __restrict__ cnorm,
    int Kcodes, int* __restrict__ idx_out, float* __restrict__ idxf_out)
{
    __shared__ float smem[SMEMF];
    vq_block(feat, cb, rown_, cnorm, Kcodes, idx_out, idxf_out,
             blockIdx.x * TBM, smem);
}

// ---------------- helpers ----------------
__device__ __forceinline__ float blockReduceSum128(float v)
{
    __shared__ float sm[128];
    int t = threadIdx.x;
    sm[t] = v;
    __syncthreads();
    for (int s = 64; s > 0; s >>= 1) {
        if (t < s) sm[t] += sm[t + s];
        __syncthreads();
    }
    float r = sm[0];
    __syncthreads();
    return r;
}

__global__ __launch_bounds__(128) void rownorm(const float* __restrict__ X,
                                               float* __restrict__ out)
{
    int row = blockIdx.x;
    int t = threadIdx.x;
    float4 v = ((const float4*)(X + (size_t)row * DDIM))[t];
    float s = v.x * v.x + v.y * v.y + v.z * v.z + v.w * v.w;
    float tot = blockReduceSum128(s);
    if (t == 0) out[row] = tot;
}

__global__ __launch_bounds__(128) void resid_loss(
    const float* __restrict__ tf, const float* __restrict__ ef,
    const float* __restrict__ df,
    const float* __restrict__ tcb, const float* __restrict__ ecb,
    const float* __restrict__ cb0,
    const int* __restrict__ idx,
    float* __restrict__ resid, float* __restrict__ rownR,
    float* __restrict__ lacc)
{
    int n = blockIdx.x;
    int t = threadIdx.x;
    int it = idx[0 * NTOK + n];
    int ie = idx[1 * NTOK + n];
    int i0 = idx[2 * NTOK + n];

    float4 a, c;
    a = ((const float4*)(tf + (size_t)n * DDIM))[t];
    c = ((const float4*)(tcb + (size_t)it * DDIM))[t];
    float dx = c.x - a.x, dy = c.y - a.y, dz = c.z - a.z, dw = c.w - a.w;
    float st = dx * dx + dy * dy + dz * dz + dw * dw;

    a = ((const float4*)(ef + (size_t)n * DDIM))[t];
    c = ((const float4*)(ecb + (size_t)ie * DDIM))[t];
    dx = c.x - a.x; dy = c.y - a.y; dz = c.z - a.z; dw = c.w - a.w;
    float se = dx * dx + dy * dy + dz * dz + dw * dw;

    a = ((const float4*)(df + (size_t)n * DDIM))[t];
    c = ((const float4*)(cb0 + (size_t)i0 * DDIM))[t];
    float4 r;
    r.x = a.x - c.x; r.y = a.y - c.y; r.z = a.z - c.z; r.w = a.w - c.w;
    ((float4*)(resid + (size_t)n * DDIM))[t] = r;
    float sr = r.x * r.x + r.y * r.y + r.z * r.z + r.w * r.w;

    float tt = blockReduceSum128(st);
    if (t == 0) atomicAdd(&lacc[0], tt);
    float te = blockReduceSum128(se);
    if (t == 0) atomicAdd(&lacc[1], te);
    float tr = blockReduceSum128(sr);
    if (t == 0) { atomicAdd(&lacc[2], tr); rownR[n] = tr; }
}

__global__ __launch_bounds__(128) void finalize_out(
    const float* __restrict__ E,
    const float* __restrict__ outb,
    const float* __restrict__ cb1,
    const float* __restrict__ resid,
    const int* __restrict__ idx,
    float* __restrict__ qout,
    float* __restrict__ lacc)
{
    int n = blockIdx.x;
    int t = threadIdx.x;
    int it = idx[0 * NTOK + n];
    int ie = idx[1 * NTOK + n];
    int i0 = idx[2 * NTOK + n];
    int i1 = idx[3 * NTOK + n];

    const float4* Et = (const float4*)(E + (size_t)it * DDIM);
    const float4* Ee = (const float4*)(E + (size_t)(KT + ie) * DDIM);
    const float4* E0 = (const float4*)(E + (size_t)(KT + KE + i0) * DDIM);
    const float4* E1 = (const float4*)(E + (size_t)(KT + KE + KD + i1) * DDIM);
    const float4* Bb = (const float4*)outb;

    float4 q;
    float4 v0 = Et[t], v1 = Ee[t], v2 = E0[t], v3 = E1[t], vb = Bb[t];
    q.x = v0.x + v1.x + v2.x + v3.x + vb.x;
    q.y = v0.y + v1.y + v2.y + v3.y + vb.y;
    q.z = v0.z + v1.z + v2.z + v3.z + vb.z;
    q.w = v0.w + v1.w + v2.w + v3.w + vb.w;
    ((float4*)(qout + (size_t)n * DDIM))[t] = q;

    float4 c = ((const float4*)(cb1 + (size_t)i1 * DDIM))[t];
    float4 r = ((const float4*)(resid + (size_t)n * DDIM))[t];
    float dx = c.x - r.x, dy = c.y - r.y, dz = c.z - r.z, dw = c.w - r.w;
    float s1 = dx * dx + dy * dy + dz * dz + dw * dw;
    float ts = blockReduceSum128(s1);
    if (t == 0) atomicAdd(&lacc[3], ts);
}

__global__ void zero_lacc(float* lacc)
{
    if (threadIdx.x < 4) lacc[threadIdx.x] = 0.f;
}

__global__ void write_loss(const float* __restrict__ lacc, float* __restrict__ out)
{
    if (threadIdx.x == 0) {
        float total = lacc[0] + lacc[1] + lacc[2] + lacc[3];
        out[0] = 1.25f * total * (1.0f / ((float)NTOK * (float)DDIM));
    }
}

// ---------------- host ----------------
extern "C" void kernel_launch(void* const* d_in, const int* in_sizes, int n_in,
                              void* d_out, int out_size)
{
    const float* x   = (const float*)d_in[0];
    const float* tW  = (const float*)d_in[1];
    const float* tb  = (const float*)d_in[2];
    const float* eW  = (const float*)d_in[3];
    const float* eb  = (const float*)d_in[4];
    const float* dW  = (const float*)d_in[5];
    const float* db  = (const float*)d_in[6];
    const float* oW  = (const float*)d_in[7];
    const float* ob  = (const float*)d_in[8];
    const float* tcb = (const float*)d_in[9];
    const float* ecb = (const float*)d_in[10];
    const float* cb0 = (const float*)d_in[11];
    const float* cb1 = (const float*)d_in[12];

    float* out = (float*)d_out;
    float* q_out    = out;                               // [NTOK*DDIM]
    float* idxf     = out + (size_t)NTOK * DDIM;         // 4x [NTOK]
    float* loss_out = idxf + (size_t)4 * NTOK;           // [1]

    float *tfeat, *efeat, *dfeat, *resid, *rown, *E, *cn, *lacc;
    int* idx;
    cudaGetSymbolAddress((void**)&tfeat, g_tfeat);
    cudaGetSymbolAddress((void**)&efeat, g_efeat);
    cudaGetSymbolAddress((void**)&dfeat, g_dfeat);
    cudaGetSymbolAddress((void**)&resid, g_resid);
    cudaGetSymbolAddress((void**)&rown,  g_rown);
    cudaGetSymbolAddress((void**)&idx,   g_idx);
    cudaGetSymbolAddress((void**)&E,     g_E);
    cudaGetSymbolAddress((void**)&cn,    g_cn);
    cudaGetSymbolAddress((void**)&lacc,  g_lacc);

    zero_lacc<<<1, 32>>>(lacc);

    // 3 feature linears in one launch
    dim3 gfeat(DDIM / TBN, NTOK / TBM, 3);
    feat3_gemm<<<gfeat, 128>>>(x, tW, tb, eW, eb, dW, db, tfeat, efeat, dfeat);

    // row norms of features
    rownorm<<<NTOK, 128>>>(tfeat, rown + 0 * NTOK);
    rownorm<<<NTOK, 128>>>(efeat, rown + 1 * NTOK);
    rownorm<<<NTOK, 128>>>(dfeat, rown + 2 * NTOK);

    // codebook norms
    rownorm<<<KT, 128>>>(tcb, cn + 0);
    rownorm<<<KE, 128>>>(ecb, cn + KT);
    rownorm<<<KD, 128>>>(cb0, cn + KT + KE);
    rownorm<<<KD, 128>>>(cb1, cn + KT + KE + KD);

    // projected codebooks: E = cb @ oW_slice^T (out_W is [512,1536] row-major)
    dim3 gEt(DDIM / TBN, KT / TBM), gEe(DDIM / TBN, KE / TBM), gEd(DDIM / TBN, KD / TBM);
    sgemm_k<<<gEt, 128>>>(tcb, DDIM, oW + 0,        3 * DDIM, nullptr,
                          E + (size_t)0 * DDIM,              DDIM, DDIM);
    sgemm_k<<<gEe, 128>>>(ecb, DDIM, oW + DDIM,     3 * DDIM, nullptr,
                          E + (size_t)KT * DDIM,             DDIM, DDIM);
    sgemm_k<<<gEd, 128>>>(cb0, DDIM, oW + 2 * DDIM, 3 * DDIM, nullptr,
                          E + (size_t)(KT + KE) * DDIM,      DDIM, DDIM);
    sgemm_k<<<gEd, 128>>>(cb1, DDIM, oW + 2 * DDIM, 3 * DDIM, nullptr,
                          E + (size_t)(KT + KE + KD) * DDIM, DDIM, DDIM);

    // first 3 VQ stages fused
    dim3 gvq(NTOK / TBM, 3);
    vq3<<<gvq, 128>>>(tfeat, efeat, dfeat, tcb, ecb, cb0, rown, cn, idx, idxf);

    // residual + losses for first three quantizers
    resid_loss<<<NTOK, 128>>>(tfeat, efeat, dfeat, tcb, ecb, cb0, idx,
                              resid, rown + 3 * NTOK, lacc);

    // second detail stage on residual
    vq1<<<NTOK / TBM, 128>>>(resid, cb1, rown + 3 * NTOK,
                             cn + KT + KE + KD, KD,
                             idx + 3 * NTOK, idxf + 3 * NTOK);

    // gather-add projected codebooks -> quantized output; stage-1 loss
    finalize_out<<<NTOK, 128>>>(E, ob, cb1, resid, idx, q_out, lacc);

    write_loss<<<1, 32>>>(lacc, loss_out);
}

// round 5
// speedup vs baseline: 1.4494x; 1.0009x over previous
#include <cuda_runtime.h>

#define NTOK 65536
#define DDIM 512
#define KT 512
#define KE 256
#define KD 512
#define KTOT (KT + KE + KD + KD)

// ---------------- scratch (device globals; no runtime alloc) ----------------
__device__ float g_tfeat[(size_t)NTOK * DDIM];
__device__ float g_efeat[(size_t)NTOK * DDIM];
__device__ float g_dfeat[(size_t)NTOK * DDIM];
__device__ float g_resid[(size_t)NTOK * DDIM];
__device__ float g_rown[4 * NTOK];          // |f|^2 per token per stage
__device__ int   g_idx[4 * NTOK];           // argmin indices per stage
__device__ float g_E[(size_t)KTOT * DDIM];  // projected codebooks Et,Ee,E0,E1
__device__ float g_cn[KTOT];                // |c|^2 per code
__device__ float g_lacc[4];                 // loss sum accumulators

// ---------------- packed fp32x2 helpers ----------------
#define FMA2(d, a, b) asm("fma.rn.f32x2 %0, %1, %2, %0;" : "+l"(d) : "l"(a), "l"(b))
#define PACK2(d, x, y) asm("mov.b64 %0, {%1, %2};" : "=l"(d) : "f"(x), "f"(y))
#define UNPACK2(x, y, d) asm("mov.b64 {%0, %1}, %2;" : "=f"(x), "=f"(y) : "l"(d))

// ---------------- 128x128x16 tile, 128 threads, 16x8 micro-tile --------------
#define TBM 128
#define TBN 128
#define TBK 16
#define PADW 132
#define STAGE (2 * TBK * PADW)   // As + Bs, one stage (floats)
#define SMEMF (2 * STAGE)        // double buffered

__device__ __forceinline__ void ldg_tile(const float* Ap, const float* Bp,
                                         int lda, int ldb, int ko,
                                         float4 a[4], float4 b[4])
{
    #pragma unroll
    for (int p = 0; p < 4; p++) {
        a[p] = *(const float4*)(Ap + (size_t)(32 * p) * lda + ko);
        b[p] = *(const float4*)(Bp + (size_t)(32 * p) * ldb + ko);
    }
}

__device__ __forceinline__ void sts_tile(float* s, int str, int sto,
                                         const float4 a[4], const float4 b[4])
{
    float* As_ = s;
    float* Bs_ = s + TBK * PADW;
    #pragma unroll
    for (int p = 0; p < 4; p++) {
        int r = str + 32 * p;
        As_[(sto + 0) * PADW + r] = a[p].x;
        As_[(sto + 1) * PADW + r] = a[p].y;
        As_[(sto + 2) * PADW + r] = a[p].z;
        As_[(sto + 3) * PADW + r] = a[p].w;
        Bs_[(sto + 0) * PADW + r] = b[p].x;
        Bs_[(sto + 1) * PADW + r] = b[p].y;
        Bs_[(sto + 2) * PADW + r] = b[p].z;
        Bs_[(sto + 3) * PADW + r] = b[p].w;
    }
}

// acc[ip][j]: row-pair ip (rows tm*16+2ip, +2ip+1) x col j (tn*8+j)
__device__ __forceinline__ void mm_tile(const float* s, int tm, int tn,
                                        unsigned long long acc[8][8])
{
    const float* As_ = s;
    const float* Bs_ = s + TBK * PADW;
    #pragma unroll
    for (int k = 0; k < TBK; k++) {
        const float* ap = &As_[k * PADW + tm * 16];
        const float* bp = &Bs_[k * PADW + tn * 8];
        float4 a0 = *(const float4*)ap;
        float4 a1 = *(const float4*)(ap + 4);
        float4 a2 = *(const float4*)(ap + 8);
        float4 a3 = *(const float4*)(ap + 12);
        float4 b0 = *(const float4*)bp;
        float4 b1 = *(const float4*)(bp + 4);
        unsigned long long ap8[8];
        PACK2(ap8[0], a0.x, a0.y); PACK2(ap8[1], a0.z, a0.w);
        PACK2(ap8[2], a1.x, a1.y); PACK2(ap8[3], a1.z, a1.w);
        PACK2(ap8[4], a2.x, a2.y); PACK2(ap8[5], a2.z, a2.w);
        PACK2(ap8[6], a3.x, a3.y); PACK2(ap8[7], a3.z, a3.w);
        float bv[8] = {b0.x, b0.y, b0.z, b0.w, b1.x, b1.y, b1.z, b1.w};
        #pragma unroll
        for (int j = 0; j < 8; j++) {
            unsigned long long bb;
            PACK2(bb, bv[j], bv[j]);
            #pragma unroll
            for (int i = 0; i < 8; i++)
                FMA2(acc[i][j], ap8[i], bb);
        }
    }
}

// C[m][n] = sum_k A[m*lda+k]*B[n*ldb+k] (+ bias[n]); block tile at (row0,col0)
__device__ __forceinline__ void gemm_block(
    const float* A, int lda, const float* B, int ldb,
    const float* bias, float* C, int ldc, int Kd,
    int row0, int col0, float* smem)
{
    int t = threadIdx.x;
    int tm = t >> 4, tn = t & 15;
    int str = t >> 2, sto = (t & 3) * 4;
    const float* Ap = A + (size_t)(row0 + str) * lda + sto;
    const float* Bp = B + (size_t)(col0 + str) * ldb + sto;

    unsigned long long acc[8][8] = {};
    float4 ar[4], br[4];
    ldg_tile(Ap, Bp, lda, ldb, 0, ar, br);
    sts_tile(smem, str, sto, ar, br);
    __syncthreads();
    int nt = Kd / TBK;
    for (int kt = 0; kt < nt; kt++) {
        if (kt + 1 < nt) ldg_tile(Ap, Bp, lda, ldb, (kt + 1) * TBK, ar, br);
        mm_tile(smem + (kt & 1) * STAGE, tm, tn, acc);
        if (kt + 1 < nt) sts_tile(smem + ((kt + 1) & 1) * STAGE, str, sto, ar, br);
        __syncthreads();
    }
    #pragma unroll
    for (int ip = 0; ip < 8; ip++) {
        float lo[8], hi[8];
        #pragma unroll
        for (int j = 0; j < 8; j++) UNPACK2(lo[j], hi[j], acc[ip][j]);
        int r0 = row0 + tm * 16 + 2 * ip;
        int c0 = col0 + tn * 8;
        if (bias) {
            #pragma unroll
            for (int j = 0; j < 8; j++) {
                float bb = bias[c0 + j];
                lo[j] += bb; hi[j] += bb;
            }
        }
        float4 w0 = {lo[0], lo[1], lo[2], lo[3]};
        float4 w1 = {lo[4], lo[5], lo[6], lo[7]};
        float4 w2 = {hi[0], hi[1], hi[2], hi[3]};
        float4 w3 = {hi[4], hi[5], hi[6], hi[7]};
        *(float4*)(C + (size_t)r0 * ldc + c0) = w0;
        *(float4*)(C + (size_t)r0 * ldc + c0 + 4) = w1;
        *(float4*)(C + (size_t)(r0 + 1) * ldc + c0) = w2;
        *(float4*)(C + (size_t)(r0 + 1) * ldc + c0 + 4) = w3;
    }
}

// fused 3 feature linears: z selects (W, b, out)
__global__ __launch_bounds__(128, 2) void feat3_gemm(
    const float* __restrict__ x,
    const float* __restrict__ tW, const float* __restrict__ tb,
    const float* __restrict__ eW, const float* __restrict__ eb,
    const float* __restrict__ dW, const float* __restrict__ db,
    float* __restrict__ tf, float* __restrict__ ef, float* __restrict__ df)
{
    __shared__ float smem[SMEMF];
    int z = blockIdx.z;
    const float* W = (z == 0) ? tW : (z == 1) ? eW : dW;
    const float* b = (z == 0) ? tb : (z == 1) ? eb : db;
    float* C = (z == 0) ? tf : (z == 1) ? ef : df;
    gemm_block(x, DDIM, W, DDIM, b, C, DDIM, DDIM,
               blockIdx.y * TBM, blockIdx.x * TBN, smem);
}

// generic (used for the small E-projection GEMMs)
__global__ __launch_bounds__(128, 2) void sgemm_k(
    const float* __restrict__ A, int lda,
    const float* __restrict__ B, int ldb,
    const float* __restrict__ bias,
    float* __restrict__ C, int ldc, int Kd)
{
    __shared__ float smem[SMEMF];
    gemm_block(A, lda, B, ldb, bias, C, ldc, Kd,
               blockIdx.y * TBM, blockIdx.x * TBN, smem);
}

// ---------------- fused distance GEMM + rowwise argmin ----------------
__device__ __forceinline__ void vq_block(
    const float* feat, const float* cb, const float* rown_,
    const float* cnorm, int Kcodes,
    int* idx_out, float* idxf_out, int row0, float* smem)
{
    int t = threadIdx.x;
    int tm = t >> 4, tn = t & 15;
    int str = t >> 2, sto = (t & 3) * 4;
    const float* Ap = feat + (size_t)(row0 + str) * DDIM + sto;

    float bestv[16];
    int bidx[16];
    #pragma unroll
    for (int i = 0; i < 16; i++) { bestv[i] = 3.4e38f; bidx[i] = 0; }

    const int nt = DDIM / TBK;
    for (int nc = 0; nc < Kcodes; nc += TBN) {
        const float* Bp = cb + (size_t)(nc + str) * DDIM + sto;
        unsigned long long acc[8][8] = {};
        float4 ar[4], br[4];
        ldg_tile(Ap, Bp, DDIM, DDIM, 0, ar, br);
        sts_tile(smem, str, sto, ar, br);
        __syncthreads();
        for (int kt = 0; kt < nt; kt++) {
            if (kt + 1 < nt) ldg_tile(Ap, Bp, DDIM, DDIM, (kt + 1) * TBK, ar, br);
            mm_tile(smem + (kt & 1) * STAGE, tm, tn, acc);
            if (kt + 1 < nt) sts_tile(smem + ((kt + 1) & 1) * STAGE, str, sto, ar, br);
            __syncthreads();
        }
        float cw[8];
        #pragma unroll
        for (int j = 0; j < 8; j++) cw[j] = cnorm[nc + tn * 8 + j];
        #pragma unroll
        for (int ip = 0; ip < 8; ip++) {
            float lo[8], hi[8];
            #pragma unroll
            for (int j = 0; j < 8; j++) UNPACK2(lo[j], hi[j], acc[ip][j]);
            float An0 = rown_[row0 + tm * 16 + 2 * ip];
            float An1 = rown_[row0 + tm * 16 + 2 * ip + 1];
            #pragma unroll
            for (int j = 0; j < 8; j++) {
                int code = nc + tn * 8 + j;
                float d0 = (An0 + cw[j]) - 2.0f * lo[j];
                if (d0 < bestv[2 * ip]) { bestv[2 * ip] = d0; bidx[2 * ip] = code; }
                float d1 = (An1 + cw[j]) - 2.0f * hi[j];
                if (d1 < bestv[2 * ip + 1]) { bestv[2 * ip + 1] = d1; bidx[2 * ip + 1] = code; }
            }
        }
    }

    // cross-thread reduce (alias smem; safe after loop-final barrier)
    float* sval = smem;                 // [128][16]
    int*   sidx = (int*)(smem + 2048);  // [128][16]
    #pragma unroll
    for (int i = 0; i < 16; i++) {
        sval[(tm * 16 + i) * 16 + tn] = bestv[i];
        sidx[(tm * 16 + i) * 16 + tn] = bidx[i];
    }
    __syncthreads();
    if (t < TBM) {
        float bv = 3.4e38f;
        int bi = 0x7fffffff;
        #pragma unroll
        for (int c = 0; c < 16; c++) {
            float v = sval[t * 16 + c];
            int id = sidx[t * 16 + c];
            if (v < bv || (v == bv && id < bi)) { bv = v; bi = id; }
        }
        idx_out[row0 + t] = bi;
        idxf_out[row0 + t] = (float)bi;
    }
}

// fused first-3 VQ stages (y selects stage)
__global__ __launch_bounds__(128, 2) void vq3(
    const float* __restrict__ tf, const float* __restrict__ ef,
    const float* __restrict__ df,
    const float* __restrict__ tcb, const float* __restrict__ ecb,
    const float* __restrict__ cb0,
    const float* __restrict__ rown_, const float* __restrict__ cn_,
    int* __restrict__ idx_, float* __restrict__ idxf_)
{
    __shared__ float smem[SMEMF];
    int s = blockIdx.y;
    const float* feat = (s == 0) ? tf : (s == 1) ? ef : df;
    const float* cb   = (s == 0) ? tcb : (s == 1) ? ecb : cb0;
    const float* rn   = rown_ + s * NTOK;
    const float* cn   = (s == 0) ? cn_ : (s == 1) ? (cn_ + KT) : (cn_ + KT + KE);
    int Kc            = (s == 1) ? KE : KT;
    vq_block(feat, cb, rn, cn, Kc, idx_ + s * NTOK, idxf_ + s * NTOK,
             blockIdx.x * TBM, smem);
}

__global__ __launch_bounds__(128, 2) void vq1(
    const float* __restrict__ feat, const float* __restrict__ cb,
    const float* __restrict__ rown_, const float* __restrict__ cnorm,
    int Kcodes, int* __restrict__ idx_out, float* __restrict__ idxf_out)
{
    __shared__ float smem[SMEMF];
    vq_block(feat, cb, rown_, cnorm, Kcodes, idx_out, idxf_out,
             blockIdx.x * TBM, smem);
}

// ---------------- helpers ----------------
__device__ __forceinline__ float blockReduceSum128(float v)
{
    __shared__ float sm[128];
    int t = threadIdx.x;
    sm[t] = v;
    __syncthreads();
    for (int s = 64; s > 0; s >>= 1) {
        if (t < s) sm[t] += sm[t + s];
        __syncthreads();
    }
    float r = sm[0];
    __syncthreads();
    return r;
}

__global__ __launch_bounds__(128) void rownorm(const float* __restrict__ X,
                                               float* __restrict__ out)
{
    int row = blockIdx.x;
    int t = threadIdx.x;
    float4 v = ((const float4*)(X + (size_t)row * DDIM))[t];
    float s = v.x * v.x + v.y * v.y + v.z * v.z + v.w * v.w;
    float tot = blockReduceSum128(s);
    if (t == 0) out[row] = tot;
}

__global__ __launch_bounds__(128) void resid_loss(
    const float* __restrict__ tf, const float* __restrict__ ef,
    const float* __restrict__ df,
    const float* __restrict__ tcb, const float* __restrict__ ecb,
    const float* __restrict__ cb0,
    const int* __restrict__ idx,
    float* __restrict__ resid, float* __restrict__ rownR,
    float* __restrict__ lacc)
{
    int n = blockIdx.x;
    int t = threadIdx.x;
    int it = idx[0 * NTOK + n];
    int ie = idx[1 * NTOK + n];
    int i0 = idx[2 * NTOK + n];

    float4 a, c;
    a = ((const float4*)(tf + (size_t)n * DDIM))[t];
    c = ((const float4*)(tcb + (size_t)it * DDIM))[t];
    float dx = c.x - a.x, dy = c.y - a.y, dz = c.z - a.z, dw = c.w - a.w;
    float st = dx * dx + dy * dy + dz * dz + dw * dw;

    a = ((const float4*)(ef + (size_t)n * DDIM))[t];
    c = ((const float4*)(ecb + (size_t)ie * DDIM))[t];
    dx = c.x - a.x; dy = c.y - a.y; dz = c.z - a.z; dw = c.w - a.w;
    float se = dx * dx + dy * dy + dz * dz + dw * dw;

    a = ((const float4*)(df + (size_t)n * DDIM))[t];
    c = ((const float4*)(cb0 + (size_t)i0 * DDIM))[t];
    float4 r;
    r.x = a.x - c.x; r.y = a.y - c.y; r.z = a.z - c.z; r.w = a.w - c.w;
    ((float4*)(resid + (size_t)n * DDIM))[t] = r;
    float sr = r.x * r.x + r.y * r.y + r.z * r.z + r.w * r.w;

    float tt = blockReduceSum128(st);
    if (t == 0) atomicAdd(&lacc[0], tt);
    float te = blockReduceSum128(se);
    if (t == 0) atomicAdd(&lacc[1], te);
    float tr = blockReduceSum128(sr);
    if (t == 0) { atomicAdd(&lacc[2], tr); rownR[n] = tr; }
}

__global__ __launch_bounds__(128) void finalize_out(
    const float* __restrict__ E,
    const float* __restrict__ outb,
    const float* __restrict__ cb1,
    const float* __restrict__ resid,
    const int* __restrict__ idx,
    float* __restrict__ qout,
    float* __restrict__ lacc)
{
    int n = blockIdx.x;
    int t = threadIdx.x;
    int it = idx[0 * NTOK + n];
    int ie = idx[1 * NTOK + n];
    int i0 = idx[2 * NTOK + n];
    int i1 = idx[3 * NTOK + n];

    const float4* Et = (const float4*)(E + (size_t)it * DDIM);
    const float4* Ee = (const float4*)(E + (size_t)(KT + ie) * DDIM);
    const float4* E0 = (const float4*)(E + (size_t)(KT + KE + i0) * DDIM);
    const float4* E1 = (const float4*)(E + (size_t)(KT + KE + KD + i1) * DDIM);
    const float4* Bb = (const float4*)outb;

    float4 q;
    float4 v0 = Et[t], v1 = Ee[t], v2 = E0[t], v3 = E1[t], vb = Bb[t];
    q.x = v0.x + v1.x + v2.x + v3.x + vb.x;
    q.y = v0.y + v1.y + v2.y + v3.y + vb.y;
    q.z = v0.z + v1.z + v2.z + v3.z + vb.z;
    q.w = v0.w + v1.w + v2.w + v3.w + vb.w;
    ((float4*)(qout + (size_t)n * DDIM))[t] = q;

    float4 c = ((const float4*)(cb1 + (size_t)i1 * DDIM))[t];
    float4 r = ((const float4*)(resid + (size_t)n * DDIM))[t];
    float dx = c.x - r.x, dy = c.y - r.y, dz = c.z - r.z, dw = c.w - r.w;
    float s1 = dx * dx + dy * dy + dz * dz + dw * dw;
    float ts = blockReduceSum128(s1);
    if (t == 0) atomicAdd(&lacc[3], ts);
}

__global__ void zero_lacc(float* lacc)
{
    if (threadIdx.x < 4) lacc[threadIdx.x] = 0.f;
}

__global__ void write_loss(const float* __restrict__ lacc, float* __restrict__ out)
{
    if (threadIdx.x == 0) {
        float total = lacc[0] + lacc[1] + lacc[2] + lacc[3];
        out[0] = 1.25f * total * (1.0f / ((float)NTOK * (float)DDIM));
    }
}

// ---------------- host ----------------
extern "C" void kernel_launch(void* const* d_in, const int* in_sizes, int n_in,
                              void* d_out, int out_size)
{
    const float* x   = (const float*)d_in[0];
    const float* tW  = (const float*)d_in[1];
    const float* tb  = (const float*)d_in[2];
    const float* eW  = (const float*)d_in[3];
    const float* eb  = (const float*)d_in[4];
    const float* dW  = (const float*)d_in[5];
    const float* db  = (const float*)d_in[6];
    const float* oW  = (const float*)d_in[7];
    const float* ob  = (const float*)d_in[8];
    const float* tcb = (const float*)d_in[9];
    const float* ecb = (const float*)d_in[10];
    const float* cb0 = (const float*)d_in[11];
    const float* cb1 = (const float*)d_in[12];

    float* out = (float*)d_out;
    float* q_out    = out;                               // [NTOK*DDIM]
    float* idxf     = out + (size_t)NTOK * DDIM;         // 4x [NTOK]
    float* loss_out = idxf + (size_t)4 * NTOK;           // [1]

    float *tfeat, *efeat, *dfeat, *resid, *rown, *E, *cn, *lacc;
    int* idx;
    cudaGetSymbolAddress((void**)&tfeat, g_tfeat);
    cudaGetSymbolAddress((void**)&efeat, g_efeat);
    cudaGetSymbolAddress((void**)&dfeat, g_dfeat);
    cudaGetSymbolAddress((void**)&resid, g_resid);
    cudaGetSymbolAddress((void**)&rown,  g_rown);
    cudaGetSymbolAddress((void**)&idx,   g_idx);
    cudaGetSymbolAddress((void**)&E,     g_E);
    cudaGetSymbolAddress((void**)&cn,    g_cn);
    cudaGetSymbolAddress((void**)&lacc,  g_lacc);

    zero_lacc<<<1, 32>>>(lacc);

    // 3 feature linears in one launch
    dim3 gfeat(DDIM / TBN, NTOK / TBM, 3);
    feat3_gemm<<<gfeat, 128>>>(x, tW, tb, eW, eb, dW, db, tfeat, efeat, dfeat);

    // row norms of features
    rownorm<<<NTOK, 128>>>(tfeat, rown + 0 * NTOK);
    rownorm<<<NTOK, 128>>>(efeat, rown + 1 * NTOK);
    rownorm<<<NTOK, 128>>>(dfeat, rown + 2 * NTOK);

    // codebook norms
    rownorm<<<KT, 128>>>(tcb, cn + 0);
    rownorm<<<KE, 128>>>(ecb, cn + KT);
    rownorm<<<KD, 128>>>(cb0, cn + KT + KE);
    rownorm<<<KD, 128>>>(cb1, cn + KT + KE + KD);

    // projected codebooks: E = cb @ oW_slice^T (out_W is [512,1536] row-major)
    dim3 gEt(DDIM / TBN, KT / TBM), gEe(DDIM / TBN, KE / TBM), gEd(DDIM / TBN, KD / TBM);
    sgemm_k<<<gEt, 128>>>(tcb, DDIM, oW + 0,        3 * DDIM, nullptr,
                          E + (size_t)0 * DDIM,              DDIM, DDIM);
    sgemm_k<<<gEe, 128>>>(ecb, DDIM, oW + DDIM,     3 * DDIM, nullptr,
                          E + (size_t)KT * DDIM,             DDIM, DDIM);
    sgemm_k<<<gEd, 128>>>(cb0, DDIM, oW + 2 * DDIM, 3 * DDIM, nullptr,
                          E + (size_t)(KT + KE) * DDIM,      DDIM, DDIM);
    sgemm_k<<<gEd, 128>>>(cb1, DDIM, oW + 2 * DDIM, 3 * DDIM, nullptr,
                          E + (size_t)(KT + KE + KD) * DDIM, DDIM, DDIM);

    // first 3 VQ stages fused
    dim3 gvq(NTOK / TBM, 3);
    vq3<<<gvq, 128>>>(tfeat, efeat, dfeat, tcb, ecb, cb0, rown, cn, idx, idxf);

    // residual + losses for first three quantizers
    resid_loss<<<NTOK, 128>>>(tfeat, efeat, dfeat, tcb, ecb, cb0, idx,
                              resid, rown + 3 * NTOK, lacc);

    // second detail stage on residual
    vq1<<<NTOK / TBM, 128>>>(resid, cb1, rown + 3 * NTOK,
                             cn + KT + KE + KD, KD,
                             idx + 3 * NTOK, idxf + 3 * NTOK);

    // gather-add projected codebooks -> quantized output; stage-1 loss
    finalize_out<<<NTOK, 128>>>(E, ob, cb1, resid, idx, q_out, lacc);

    write_loss<<<1, 32>>>(lacc, loss_out);
}